// round 1
// baseline (speedup 1.0000x reference)
#include <cuda_runtime.h>

// LightGCN_4440996184480 — structural simplification:
// norm == 0 for all edges (user nodes have zero in-degree), so all GCN layers
// are zero. Outputs:
//   out[0 : 32M)            = user_emb * 0.25
//   out[32M : 44.8M)        = (audio + artist_emb[aid] + album_emb[alid]) * 0.25
//   out[44.8M]              = mean((item_h/4 - audio @ W^T)^2)

#define NUM_USERS  500000
#define NUM_ITEMS  200000
#define EMBED_DIM  64
#define USER_ELEMS (NUM_USERS * EMBED_DIM)   // 32,000,000
#define ITEM_ELEMS (NUM_ITEMS * EMBED_DIM)   // 12,800,000
#define LOSS_IDX   (USER_ELEMS + ITEM_ELEMS) // 44,800,000

#define ITEM_BLOCKS 512
#define USER_BLOCKS 512
#define TOTAL_BLOCKS (ITEM_BLOCKS + USER_BLOCKS)

__device__ float g_partials[ITEM_BLOCKS];

__global__ __launch_bounds__(256) void fused_kernel(
    const float* __restrict__ user_emb,
    const float* __restrict__ artist_emb,
    const float* __restrict__ album_emb,
    const float* __restrict__ audio,
    const float* __restrict__ Wproj,       // (64,64): proj[j] = sum_k a[k]*W[j*64+k]
    const int*   __restrict__ artist_ids,
    const int*   __restrict__ album_ids,
    float*       __restrict__ out)
{
    if (blockIdx.x < ITEM_BLOCKS) {
        // ---------------- item path: gather-add + projection + loss ----------
        const int tid = threadIdx.x;
        const int g   = tid >> 6;   // 0..3: item slot within block-iteration
        const int j   = tid & 63;   // output column handled by this thread

        __shared__ float sh_a[4][64];
        __shared__ float red[256];

        // W row j resident in registers (fully unrolled accesses keep it there)
        float w[64];
        #pragma unroll
        for (int q = 0; q < 16; ++q) {
            float4 v = reinterpret_cast<const float4*>(Wproj)[j * 16 + q];
            w[4*q+0] = v.x; w[4*q+1] = v.y; w[4*q+2] = v.z; w[4*q+3] = v.w;
        }

        float lsum = 0.0f;
        float* item_out = out + USER_ELEMS;

        // NUM_ITEMS is a multiple of 4, and base advances in steps of 4*ITEM_BLOCKS,
        // so (base + g) is always in range when base < NUM_ITEMS.
        for (int base = blockIdx.x * 4; base < NUM_ITEMS; base += ITEM_BLOCKS * 4) {
            const int item = base + g;

            const float a  = audio[item * 64 + j];
            const float ar = artist_emb[artist_ids[item] * 64 + j];
            const float al = album_emb [album_ids [item] * 64 + j];
            const float d  = (a + ar + al) * 0.25f;
            item_out[item * 64 + j] = d;

            sh_a[g][j] = a;
            __syncthreads();

            // proj[j] = dot(a, W[j,:]) — 4 accumulators break the RAW chain
            float s0 = 0.f, s1 = 0.f, s2 = 0.f, s3 = 0.f;
            #pragma unroll
            for (int k = 0; k < 64; k += 4) {
                s0 += sh_a[g][k + 0] * w[k + 0];
                s1 += sh_a[g][k + 1] * w[k + 1];
                s2 += sh_a[g][k + 2] * w[k + 2];
                s3 += sh_a[g][k + 3] * w[k + 3];
            }
            const float diff = d - ((s0 + s1) + (s2 + s3));
            lsum += diff * diff;

            __syncthreads();  // protect sh_a before next iteration overwrites
        }

        // deterministic block reduction
        red[tid] = lsum;
        __syncthreads();
        #pragma unroll
        for (int off = 128; off > 0; off >>= 1) {
            if (tid < off) red[tid] += red[tid + off];
            __syncthreads();
        }
        if (tid == 0) g_partials[blockIdx.x] = red[0];
    } else {
        // ---------------- user path: scale-copy 32M floats -------------------
        const float4* in4  = reinterpret_cast<const float4*>(user_emb);
        float4*       out4 = reinterpret_cast<float4*>(out);
        const int n4  = USER_ELEMS / 4;                  // 8,000,000
        const int bid = blockIdx.x - ITEM_BLOCKS;
        const int stride = USER_BLOCKS * 256;
        for (int i = bid * 256 + threadIdx.x; i < n4; i += stride) {
            float4 v = in4[i];
            v.x *= 0.25f; v.y *= 0.25f; v.z *= 0.25f; v.w *= 0.25f;
            out4[i] = v;
        }
    }
}

__global__ void finalize_kernel(float* __restrict__ out)
{
    __shared__ float red[256];
    float s = 0.0f;
    for (int i = threadIdx.x; i < ITEM_BLOCKS; i += 256) s += g_partials[i];
    red[threadIdx.x] = s;
    __syncthreads();
    #pragma unroll
    for (int off = 128; off > 0; off >>= 1) {
        if (threadIdx.x < off) red[threadIdx.x] += red[threadIdx.x + off];
        __syncthreads();
    }
    if (threadIdx.x == 0)
        out[LOSS_IDX] = red[0] * (1.0f / (float)ITEM_ELEMS);
}

extern "C" void kernel_launch(void* const* d_in, const int* in_sizes, int n_in,
                              void* d_out, int out_size)
{
    const float* user_emb   = (const float*)d_in[0];
    const float* artist_emb = (const float*)d_in[1];
    const float* album_emb  = (const float*)d_in[2];
    const float* audio      = (const float*)d_in[3];
    const float* Wproj      = (const float*)d_in[4];
    // d_in[5..11]: mlp weights / edge data — dead (norm == 0 structurally)
    const int* artist_ids   = (const int*)d_in[12];
    const int* album_ids    = (const int*)d_in[13];
    float* out = (float*)d_out;

    fused_kernel<<<TOTAL_BLOCKS, 256>>>(user_emb, artist_emb, album_emb, audio,
                                        Wproj, artist_ids, album_ids, out);
    finalize_kernel<<<1, 256>>>(out);
}

// round 2
// speedup vs baseline: 1.4491x; 1.4491x over previous
#include <cuda_runtime.h>

// LightGCN_4440996184480 — structural simplification (verified rel_err=0):
// norm == 0 for all edges (user nodes have zero in-degree => dis[src]=0),
// so all GCN propagation layers are exactly zero.
//   out[0 : 32M)     = user_emb * 0.25
//   out[32M : 44.8M) = (audio + artist_emb[aid] + album_emb[alid]) * 0.25
//   out[44.8M]       = mean((item_h/4 - audio @ W^T)^2)
//
// R2: barrier-free item path. Each item is handled by a PAIR of independent
// warps (each owns 32 of the 64 columns, W-row in registers, audio vector
// broadcast via shuffles). No __syncthreads in the hot loop; next item's
// gather indices are prefetched during the dot product.

#define NUM_USERS  500000
#define NUM_ITEMS  200000
#define EMBED_DIM  64
#define USER_ELEMS (NUM_USERS * EMBED_DIM)   // 32,000,000
#define ITEM_ELEMS (NUM_ITEMS * EMBED_DIM)   // 12,800,000
#define LOSS_IDX   (USER_ELEMS + ITEM_ELEMS) // 44,800,000

#define ITEM_BLOCKS 592
#define USER_BLOCKS 592
#define TOTAL_BLOCKS (ITEM_BLOCKS + USER_BLOCKS)
#define NUM_PAIRS   (ITEM_BLOCKS * 4)        // item streams (2 warps each)
#define NUM_PARTIALS (ITEM_BLOCKS * 8)       // one loss partial per item warp

__device__ float g_partials[NUM_PARTIALS];

__global__ __launch_bounds__(256, 2) void fused_kernel(
    const float* __restrict__ user_emb,
    const float* __restrict__ artist_emb,
    const float* __restrict__ album_emb,
    const float* __restrict__ audio,
    const float* __restrict__ Wproj,       // (64,64) row-major: proj[j]=dot(a, W[j,:])
    const int*   __restrict__ artist_ids,
    const int*   __restrict__ album_ids,
    float*       __restrict__ out)
{
    if (blockIdx.x < ITEM_BLOCKS) {
        // ---------------- item path: warp-autonomous, barrier-free ----------
        const int tid  = threadIdx.x;
        const int warp = tid >> 5;
        const int lane = tid & 31;
        const int h    = warp & 1;                      // column half
        const int pair = blockIdx.x * 4 + (warp >> 1);  // item stream id
        const int j    = h * 32 + lane;                 // owned output column

        // W row j fully register-resident (loop fully unrolled below)
        float w[64];
        #pragma unroll
        for (int q = 0; q < 16; ++q) {
            float4 v = reinterpret_cast<const float4*>(Wproj)[j * 16 + q];
            w[4*q+0] = v.x; w[4*q+1] = v.y; w[4*q+2] = v.z; w[4*q+3] = v.w;
        }

        float  lsum = 0.0f;
        float* item_out = out + USER_ELEMS;

        int item = pair;
        int idxA = 0, idxB = 0;
        if (item < NUM_ITEMS) { idxA = artist_ids[item]; idxB = album_ids[item]; }

        while (item < NUM_ITEMS) {
            // issue all loads up front; gathers fly during the shuffle-dot
            const float a_lo = audio[item * 64 + lane];
            const float a_hi = audio[item * 64 + 32 + lane];
            const float ar   = artist_emb[idxA * 64 + j];
            const float al   = album_emb [idxB * 64 + j];

            const int nitem = item + NUM_PAIRS;
            if (nitem < NUM_ITEMS) {            // prefetch next indices
                idxA = artist_ids[nitem];
                idxB = album_ids [nitem];
            }

            // proj[j] = dot(audio_row, W[j,:]) via warp broadcast of a
            float p0 = 0.0f, p1 = 0.0f;
            #pragma unroll
            for (int k = 0; k < 32; k += 2) {
                p0 += __shfl_sync(0xffffffffu, a_lo, k)     * w[k];
                p1 += __shfl_sync(0xffffffffu, a_lo, k + 1) * w[k + 1];
            }
            #pragma unroll
            for (int k = 0; k < 32; k += 2) {
                p0 += __shfl_sync(0xffffffffu, a_hi, k)     * w[32 + k];
                p1 += __shfl_sync(0xffffffffu, a_hi, k + 1) * w[33 + k];
            }

            const float a_own = h ? a_hi : a_lo;
            const float d     = (a_own + ar + al) * 0.25f;
            item_out[item * 64 + j] = d;

            const float diff = d - (p0 + p1);
            lsum += diff * diff;

            item = nitem;
        }

        // deterministic warp reduction (fixed shuffle tree)
        #pragma unroll
        for (int off = 16; off > 0; off >>= 1)
            lsum += __shfl_xor_sync(0xffffffffu, lsum, off);
        if (lane == 0)
            g_partials[blockIdx.x * 8 + warp] = lsum;
    } else {
        // ---------------- user path: scale-copy 32M floats ------------------
        const float4* in4  = reinterpret_cast<const float4*>(user_emb);
        float4*       out4 = reinterpret_cast<float4*>(out);
        const int n4     = USER_ELEMS / 4;     // 8,000,000
        const int bid    = blockIdx.x - ITEM_BLOCKS;
        const int stride = USER_BLOCKS * 256;
        for (int i = bid * 256 + threadIdx.x; i < n4; i += stride) {
            float4 v = in4[i];
            v.x *= 0.25f; v.y *= 0.25f; v.z *= 0.25f; v.w *= 0.25f;
            out4[i] = v;
        }
    }
}

__global__ void finalize_kernel(float* __restrict__ out)
{
    __shared__ float red[256];
    float s = 0.0f;
    for (int i = threadIdx.x; i < NUM_PARTIALS; i += 256) s += g_partials[i];
    red[threadIdx.x] = s;
    __syncthreads();
    #pragma unroll
    for (int off = 128; off > 0; off >>= 1) {
        if (threadIdx.x < off) red[threadIdx.x] += red[threadIdx.x + off];
        __syncthreads();
    }
    if (threadIdx.x == 0)
        out[LOSS_IDX] = red[0] * (1.0f / (float)ITEM_ELEMS);
}

extern "C" void kernel_launch(void* const* d_in, const int* in_sizes, int n_in,
                              void* d_out, int out_size)
{
    const float* user_emb   = (const float*)d_in[0];
    const float* artist_emb = (const float*)d_in[1];
    const float* album_emb  = (const float*)d_in[2];
    const float* audio      = (const float*)d_in[3];
    const float* Wproj      = (const float*)d_in[4];
    // d_in[5..11]: mlp weights / edge data — dead (norm == 0 structurally)
    const int* artist_ids   = (const int*)d_in[12];
    const int* album_ids    = (const int*)d_in[13];
    float* out = (float*)d_out;

    fused_kernel<<<TOTAL_BLOCKS, 256>>>(user_emb, artist_emb, album_emb, audio,
                                        Wproj, artist_ids, album_ids, out);
    finalize_kernel<<<1, 256>>>(out);
}